// round 16
// baseline (speedup 1.0000x reference)
#include <cuda_runtime.h>
#include <cuda_bf16.h>
#include <cuda_fp16.h>
#include <cstdint>

#define BB 1024
#define TTT 100
#define MM 128
#define HH 128
#define PP 128
#define CC 32
#define GG 512

// ---------------- device scratch ----------------
__device__ __half g_x16[(size_t)BB * TTT * MM];             // fp16 x_tilde
__device__ __half g_G1h[(size_t)BB * TTT * GG];             // fp16 x_tilde@Wih^T
__device__ float g_Xenc[(size_t)BB * TTT * HH];
__device__ __nv_bfloat16 g_Xenc16[(size_t)BB * TTT * HH];
__device__ __nv_bfloat16 g_preX16[(size_t)BB * TTT * HH];
__device__ __half g_encWhh16[128 * GG];                     // [k][g]
__device__ __half g_decWhh16[128 * GG];                     // [k][g]
__device__ __half g_Wih16[GG * MM];                         // [g][k]
__device__ __nv_bfloat16 g_W1x16[128 * 128];                // [h][k] bf16
__device__ __half g_W1dc16[256 * HH];                       // [k][h] fp16
__device__ float g_encBias[GG];
__device__ float g_decBias[GG];

typedef unsigned long long ull;

__device__ __forceinline__ ull pack2(float x, float y) {
    ull r;
    asm("mov.b64 %0, {%1, %2};" : "=l"(r)
        : "r"(__float_as_uint(x)), "r"(__float_as_uint(y)));
    return r;
}
__device__ __forceinline__ float2 unpack2(ull v) {
    unsigned int lo, hi;
    asm("mov.b64 {%0, %1}, %2;" : "=r"(lo), "=r"(hi) : "l"(v));
    return make_float2(__uint_as_float(lo), __uint_as_float(hi));
}
__device__ __forceinline__ ull ffma2(ull a, ull b, ull c) {
    ull d;
    asm("fma.rn.f32x2 %0, %1, %2, %3;" : "=l"(d) : "l"(a), "l"(b), "l"(c));
    return d;
}
__device__ __forceinline__ float sigm(float x) {
    return 1.0f / (1.0f + __expf(-x));
}
__device__ __forceinline__ float tanh_s(float x) {
    float a = fabsf(x);
    float e = __expf(-2.0f * a);
    float r = (1.0f - e) / (1.0f + e);
    return copysignf(r, x);
}
__device__ __forceinline__ float tanh_fast(float x) {
    float y;
    asm("tanh.approx.f32 %0, %1;" : "=f"(y) : "f"(x));
    return y;
}
__device__ __forceinline__ float2 bf2f(unsigned int u) {
    __nv_bfloat162 h = *reinterpret_cast<__nv_bfloat162*>(&u);
    return __bfloat1622float2(h);
}

// ---------------- merged prep + alpha/x16 ----------------
__global__ void prep_alpha(const float* __restrict__ X, const float* __restrict__ Wa,
                           const float* __restrict__ encWih, const float* __restrict__ encWhh,
                           const float* __restrict__ decWhh, const float* __restrict__ decW1,
                           const float* __restrict__ ebih, const float* __restrict__ ebhh,
                           const float* __restrict__ dbih, const float* __restrict__ dbhh) {
    int blk = blockIdx.x, tid = threadIdx.x;
    if (blk < 964) {
        int idx = blk * 256 + tid;
        if (idx < 65536) {
            int k = idx >> 9, gg = idx & 511;
            g_encWhh16[idx] = __float2half(encWhh[gg * 128 + k]);
        } else if (idx < 131072) {
            int l = idx - 65536; int k = l >> 9, gg = l & 511;
            g_decWhh16[l] = __float2half(decWhh[gg * 128 + k]);
        } else if (idx < 196608) {
            int l = idx - 131072;
            g_Wih16[l] = __float2half(encWih[l]);
        } else if (idx < 229376) {
            int l = idx - 196608; int hh = l & 127, k = l >> 7;
            g_W1dc16[l] = __float2half(decW1[hh * 384 + k]);
        } else if (idx < 245760) {
            int l = idx - 229376; int hh = l >> 7, k = l & 127;   // [h][k]
            g_W1x16[l] = __float2bfloat16(decW1[hh * 384 + 256 + k]);
        } else if (idx < 246272) {
            int gg = idx - 245760; g_encBias[gg] = ebih[gg] + ebhh[gg];
        } else if (idx < 246784) {
            int gg = idx - 246272; g_decBias[gg] = dbih[gg] + dbhh[gg];
        }
    } else {
        __shared__ float wa[TTT];
        __shared__ float buf[2][128];
        int hf = tid >> 7, m = tid & 127;
        int b = (blk - 964) * 2 + hf;
        if (tid < TTT) wa[tid] = Wa[2 * HH + tid];
        __syncthreads();
        const float* xb = X + (size_t)b * TTT * MM + m;
        float a0 = 0.f, a1 = 0.f, a2 = 0.f, a3 = 0.f;
#pragma unroll
        for (int tt = 0; tt < TTT / 4; tt++) {
            a0 += xb[(tt * 4 + 0) * MM] * wa[tt * 4 + 0];
            a1 += xb[(tt * 4 + 1) * MM] * wa[tt * 4 + 1];
            a2 += xb[(tt * 4 + 2) * MM] * wa[tt * 4 + 2];
            a3 += xb[(tt * 4 + 3) * MM] * wa[tt * 4 + 3];
        }
        float s = (a0 + a1) + (a2 + a3);
        buf[hf][m] = s; __syncthreads();
        for (int st = 64; st > 0; st >>= 1) {
            if (m < st) buf[hf][m] = fmaxf(buf[hf][m], buf[hf][m + st]);
            __syncthreads();
        }
        float mx = buf[hf][0]; __syncthreads();
        float e = __expf(s - mx);
        buf[hf][m] = e; __syncthreads();
        for (int st = 64; st > 0; st >>= 1) {
            if (m < st) buf[hf][m] += buf[hf][m + st];
            __syncthreads();
        }
        float alpha = e / buf[hf][0];
        __half* xo = g_x16 + (size_t)b * TTT * MM + m;
#pragma unroll 4
        for (int t = 0; t < TTT; t++)
            xo[t * MM] = __float2half(xb[t * MM] * alpha);
    }
}

// ---------------- G1 = x16 @ Wih16^T via mma.sync m16n8k16 ----------------
#define G1_SMEM_BYTES (512 * 136 * 2)
__global__ __launch_bounds__(256) void gemm_g1() {
    extern __shared__ __half Bs[];      // [512][136]
    int tid = threadIdx.x, wid = tid >> 5, lane = tid & 31;
    {
        const unsigned int* src = reinterpret_cast<const unsigned int*>(g_Wih16);
        for (int i = tid; i < 32768; i += 256) {
            int n = i >> 6, kk = i & 63;
            *(reinterpret_cast<unsigned int*>(Bs + n * 136) + kk) = src[i];
        }
    }
    __syncthreads();
    int m0 = blockIdx.x * 128 + wid * 16;
    int grp = lane >> 2, tig = lane & 3;
    const __half* a0p = g_x16 + (size_t)m0 * 128 + (size_t)grp * 128 + tig * 2;

    for (int nc = 0; nc < 8; nc++) {
        float c[8][4];
#pragma unroll
        for (int nt = 0; nt < 8; nt++) {
            c[nt][0] = 0.f; c[nt][1] = 0.f; c[nt][2] = 0.f; c[nt][3] = 0.f;
        }
#pragma unroll
        for (int ks = 0; ks < 8; ks++) {
            unsigned int a0 = *reinterpret_cast<const unsigned int*>(a0p + ks * 16);
            unsigned int a1 = *reinterpret_cast<const unsigned int*>(a0p + 8 * 128 + ks * 16);
            unsigned int a2 = *reinterpret_cast<const unsigned int*>(a0p + ks * 16 + 8);
            unsigned int a3 = *reinterpret_cast<const unsigned int*>(a0p + 8 * 128 + ks * 16 + 8);
#pragma unroll
            for (int nt = 0; nt < 8; nt++) {
                int n = nc * 64 + nt * 8 + grp;
                const __half* bp = Bs + n * 136 + ks * 16 + tig * 2;
                unsigned int b0 = *reinterpret_cast<const unsigned int*>(bp);
                unsigned int b1 = *reinterpret_cast<const unsigned int*>(bp + 8);
                asm volatile(
                    "mma.sync.aligned.m16n8k16.row.col.f32.f16.f16.f32 "
                    "{%0,%1,%2,%3}, {%4,%5,%6,%7}, {%8,%9}, {%0,%1,%2,%3};"
                    : "+f"(c[nt][0]), "+f"(c[nt][1]), "+f"(c[nt][2]), "+f"(c[nt][3])
                    : "r"(a0), "r"(a1), "r"(a2), "r"(a3), "r"(b0), "r"(b1));
            }
        }
#pragma unroll
        for (int nt = 0; nt < 8; nt++) {
            int col = nc * 64 + nt * 8 + tig * 2;
            __half2 lo = __floats2half2_rn(c[nt][0], c[nt][1]);
            __half2 hi = __floats2half2_rn(c[nt][2], c[nt][3]);
            *reinterpret_cast<__half2*>(g_G1h + (size_t)(m0 + grp) * 512 + col) = lo;
            *reinterpret_cast<__half2*>(g_G1h + (size_t)(m0 + grp + 8) * 512 + col) = hi;
        }
    }
}

// ---------------- preX = Xenc16 @ W1x^T + b1 -> bf16 via bf16 mma ----------------
#define PREX_SMEM_BYTES (128 * 136 * 2)
__global__ __launch_bounds__(256) void gemm_preX16(const float* __restrict__ b1) {
    extern __shared__ __nv_bfloat16 Bx[];   // [128][136]
    __shared__ float b1s[128];
    int tid = threadIdx.x, wid = tid >> 5, lane = tid & 31;
    {
        const unsigned int* src = reinterpret_cast<const unsigned int*>(g_W1x16);
        for (int i = tid; i < 8192; i += 256) {
            int n = i >> 6, kk = i & 63;
            *(reinterpret_cast<unsigned int*>(Bx + n * 136) + kk) = src[i];
        }
        if (tid < 128) b1s[tid] = b1[tid];
    }
    __syncthreads();
    int m0 = blockIdx.x * 128 + wid * 16;
    int grp = lane >> 2, tig = lane & 3;
    const __nv_bfloat16* a0p = g_Xenc16 + (size_t)m0 * 128 + (size_t)grp * 128 + tig * 2;

    for (int nc = 0; nc < 2; nc++) {
        float c[8][4];
#pragma unroll
        for (int nt = 0; nt < 8; nt++) {
            c[nt][0] = 0.f; c[nt][1] = 0.f; c[nt][2] = 0.f; c[nt][3] = 0.f;
        }
#pragma unroll
        for (int ks = 0; ks < 8; ks++) {
            unsigned int a0 = *reinterpret_cast<const unsigned int*>(a0p + ks * 16);
            unsigned int a1 = *reinterpret_cast<const unsigned int*>(a0p + 8 * 128 + ks * 16);
            unsigned int a2 = *reinterpret_cast<const unsigned int*>(a0p + ks * 16 + 8);
            unsigned int a3 = *reinterpret_cast<const unsigned int*>(a0p + 8 * 128 + ks * 16 + 8);
#pragma unroll
            for (int nt = 0; nt < 8; nt++) {
                int n = nc * 64 + nt * 8 + grp;
                const __nv_bfloat16* bp = Bx + n * 136 + ks * 16 + tig * 2;
                unsigned int b0 = *reinterpret_cast<const unsigned int*>(bp);
                unsigned int bq = *reinterpret_cast<const unsigned int*>(bp + 8);
                asm volatile(
                    "mma.sync.aligned.m16n8k16.row.col.f32.bf16.bf16.f32 "
                    "{%0,%1,%2,%3}, {%4,%5,%6,%7}, {%8,%9}, {%0,%1,%2,%3};"
                    : "+f"(c[nt][0]), "+f"(c[nt][1]), "+f"(c[nt][2]), "+f"(c[nt][3])
                    : "r"(a0), "r"(a1), "r"(a2), "r"(a3), "r"(b0), "r"(bq));
            }
        }
#pragma unroll
        for (int nt = 0; nt < 8; nt++) {
            int col = nc * 64 + nt * 8 + tig * 2;
            float bl = b1s[col], bh = b1s[col + 1];
            __nv_bfloat162 lo = __floats2bfloat162_rn(c[nt][0] + bl, c[nt][1] + bh);
            __nv_bfloat162 hi = __floats2bfloat162_rn(c[nt][2] + bl, c[nt][3] + bh);
            *reinterpret_cast<__nv_bfloat162*>(g_preX16 + (size_t)(m0 + grp) * 128 + col) = lo;
            *reinterpret_cast<__nv_bfloat162*>(g_preX16 + (size_t)(m0 + grp + 8) * 128 + col) = hi;
        }
    }
}

// ---------------- fused encoder: K=128 recurrence, fp16 Whh (R13) ----------------
#define ENC_SMEM_FLOATS (1536 + 16384)
__global__ __launch_bounds__(1024, 1) void enc_fused() {
    extern __shared__ float es[];
    float* hT  = es;            // [128][12]
    float* gsb = es + 1536;     // [4][8][512]
    const int b0 = blockIdx.x * 8;
    const int tid = threadIdx.x;
    const int gq = tid & 127, rh = (tid >> 7) & 1, kq = tid >> 8;
    const int g0 = gq * 4, rb = rh * 4;
    const int jr = tid & 127, r = tid >> 7;
    float bia4[4];
#pragma unroll
    for (int x = 0; x < 4; x++) bia4[x] = g_encBias[jr + 128 * x];
    float c_reg = 0.f;
    hT[jr * 12 + r] = 0.f;
    const size_t xrow = (size_t)(b0 + r) * TTT;
    const uint2* wq = reinterpret_cast<const uint2*>(g_encWhh16)
                      + (size_t)(kq * 32) * 128 + gq;
    const __half* g1p = g_G1h + xrow * 512 + jr;
    __syncthreads();

    for (int t = 0; t < TTT; t++) {
        ull a00 = 0, a01 = 0, a10 = 0, a11 = 0, a20 = 0, a21 = 0, a30 = 0, a31 = 0;
        const float* xp = hT + (kq * 32) * 12 + rb;
#pragma unroll 4
        for (int k = 0; k < 32; k++) {
            uint2 wr = wq[(size_t)k * 128];
            __half2 hA = *reinterpret_cast<const __half2*>(&wr.x);
            __half2 hB = *reinterpret_cast<const __half2*>(&wr.y);
            float2 wa = __half22float2(hA);
            float2 wb = __half22float2(hB);
            ulonglong2 xr = *reinterpret_cast<const ulonglong2*>(xp + k * 12);
            ull w0 = pack2(wa.x, wa.x), w1 = pack2(wa.y, wa.y);
            ull w2 = pack2(wb.x, wb.x), w3 = pack2(wb.y, wb.y);
            a00 = ffma2(xr.x, w0, a00); a01 = ffma2(xr.y, w0, a01);
            a10 = ffma2(xr.x, w1, a10); a11 = ffma2(xr.y, w1, a11);
            a20 = ffma2(xr.x, w2, a20); a21 = ffma2(xr.y, w2, a21);
            a30 = ffma2(xr.x, w3, a30); a31 = ffma2(xr.y, w3, a31);
        }
        {
            float2 u00 = unpack2(a00), u10 = unpack2(a10), u20 = unpack2(a20), u30 = unpack2(a30);
            float2 u01 = unpack2(a01), u11 = unpack2(a11), u21 = unpack2(a21), u31 = unpack2(a31);
            float* gb = gsb + (kq * 8 + rb) * 512 + g0;
            *reinterpret_cast<float4*>(gb + 0 * 512) = make_float4(u00.x, u10.x, u20.x, u30.x);
            *reinterpret_cast<float4*>(gb + 1 * 512) = make_float4(u00.y, u10.y, u20.y, u30.y);
            *reinterpret_cast<float4*>(gb + 2 * 512) = make_float4(u01.x, u11.x, u21.x, u31.x);
            *reinterpret_cast<float4*>(gb + 3 * 512) = make_float4(u01.y, u11.y, u21.y, u31.y);
        }
        __syncthreads();
        const __half* gp = g1p + (size_t)t * 512;
        float iv = gsb[(0 + r) * 512 + jr      ] + gsb[(8 + r) * 512 + jr      ]
                 + gsb[(16 + r) * 512 + jr     ] + gsb[(24 + r) * 512 + jr     ]
                 + __half2float(gp[0])   + bia4[0];
        float fv = gsb[(0 + r) * 512 + jr + 128] + gsb[(8 + r) * 512 + jr + 128]
                 + gsb[(16 + r) * 512 + jr + 128] + gsb[(24 + r) * 512 + jr + 128]
                 + __half2float(gp[128]) + bia4[1];
        float gv = gsb[(0 + r) * 512 + jr + 256] + gsb[(8 + r) * 512 + jr + 256]
                 + gsb[(16 + r) * 512 + jr + 256] + gsb[(24 + r) * 512 + jr + 256]
                 + __half2float(gp[256]) + bia4[2];
        float ov = gsb[(0 + r) * 512 + jr + 384] + gsb[(8 + r) * 512 + jr + 384]
                 + gsb[(16 + r) * 512 + jr + 384] + gsb[(24 + r) * 512 + jr + 384]
                 + __half2float(gp[384]) + bia4[3];
        float cn = sigm(fv) * c_reg + sigm(iv) * tanh_s(gv);
        float hn = sigm(ov) * tanh_s(cn);
        c_reg = cn;
        __syncthreads();
        hT[jr * 12 + r] = hn;
        g_Xenc[(xrow + t) * HH + jr] = hn;
        g_Xenc16[(xrow + t) * HH + jr] = __float2bfloat16(hn);
        __syncthreads();
    }
}

// ---------------- fused decoder: 512 thr / 4 rows, 2 blocks per SM ----------------
// smem floats:
//   W1dc16 (fp16, as 16384 float slots) | dcatT 3072 | gsb 2048 (A partials)
//   egs 4096 (E out) | u_s 512 | ctxp 1024 | ctx_s 512 | zbuf 8 | y_s 4
//   w2_s 128 | fw_s 128
#define DEC_SMEM_FLOATS (16384 + 3072 + 2048 + 4096 + 512 + 1024 + 512 + 8 + 4 + 128 + 128)

__global__ __launch_bounds__(512, 2) void dec_fused(
    const float* __restrict__ decWih, const float* __restrict__ decW2,
    const float* __restrict__ fcW, const float* __restrict__ fcB,
    const float* __restrict__ fcfW, const float* __restrict__ fcfB,
    float* __restrict__ out)
{
    extern __shared__ float sm[];
    __half* W1dcS = reinterpret_cast<__half*>(sm);   // 32768 halves
    float* dcatT = sm + 16384;
    float* gsb   = dcatT + 3072;
    float* egs   = gsb + 2048;
    float* u_s   = egs + 4096;
    float* ctxp  = u_s + 512;
    float* ctx_s = ctxp + 1024;
    float* zbuf  = ctx_s + 512;
    float* y_s   = zbuf + 8;
    float* w2_s  = y_s + 4;
    float* fw_s  = w2_s + 128;

    const int b0 = blockIdx.x * 4;
    const int tid = threadIdx.x;
    const int lane = tid & 31, wp = tid >> 5;
    const int jr = tid & 127;
    const int r  = tid >> 7;        // 0..3: A k-slice / F row

    {   // load W1dc fp16 into smem (64 KB)
        uint4* dst = reinterpret_cast<uint4*>(W1dcS);
        const uint4* src = reinterpret_cast<const uint4*>(g_W1dc16);
        for (int i = tid; i < 4096; i += 512) dst[i] = src[i];
    }
    for (int i = tid; i < 3072; i += 512) dcatT[i] = 0.f;
    if (tid < 128) { w2_s[tid] = decW2[tid]; fw_s[tid] = fcW[tid]; }
    float wih4[4], bia4[4];
#pragma unroll
    for (int x = 0; x < 4; x++) {
        wih4[x] = decWih[jr + 128 * x];
        bia4[x] = g_decBias[jr + 128 * x];
    }
    float c_reg = 0.f;
    const float fcb = fcB[0];
    // E-phase constants (threads 256..511)
    const int ti = tid - 256;
    const int gqE = ti & 127, khE = (tid >= 256) ? (ti >> 7) : 0;
    const int g0E = gqE * 4;
    const uint2* wqh = reinterpret_cast<const uint2*>(g_decWhh16)
                       + (size_t)(khE * 64) * 128 + gqE;
    __syncthreads();
    const float4 w2v = *reinterpret_cast<const float4*>(&w2_s[lane * 4]);
    const float4 fwv = *reinterpret_cast<const float4*>(&fw_s[lane * 4]);

    for (int t = 0; t < TTT; t++) {
        // ---- A: u partials = [d;cc] @ W1dc^T (k-slice r*64..+63 per thread)
        {
            ull a0 = 0, a1 = 0;
            const __half* wA = W1dcS + (r * 64) * 128 + jr;
            const float* dk = dcatT + (r * 64) * 12;
#pragma unroll 8
            for (int kk = 0; kk < 64; kk++) {
                float w = __half2float(wA[kk * 128]);
                ull ww = pack2(w, w);
                ulonglong2 p = *reinterpret_cast<const ulonglong2*>(dk + kk * 12);
                a0 = ffma2(p.x, ww, a0);
                a1 = ffma2(p.y, ww, a1);
            }
            float2 f0 = unpack2(a0), f1 = unpack2(a1);
            gsb[(r * 4 + 0) * 128 + jr] = f0.x;
            gsb[(r * 4 + 1) * 128 + jr] = f0.y;
            gsb[(r * 4 + 2) * 128 + jr] = f1.x;
            gsb[(r * 4 + 3) * 128 + jr] = f1.y;
        }
        __syncthreads();
        {
            float u = gsb[(0 + r) * 128 + jr] + gsb[(4 + r) * 128 + jr]
                    + gsb[(8 + r) * 128 + jr] + gsb[(12 + r) * 128 + jr];
            u_s[r * 128 + jr] = u;
        }
        __syncthreads();

        // ---- parallel: B (scores+ctx+z, warps 0-7) | E (LSTM GEMM, warps 8-15)
        if (tid < 256) {
            const int rw = wp & 3, fh = wp >> 2;
            float4 uv = *reinterpret_cast<const float4*>(&u_s[rw * 128 + lane * 4]);
            const __nv_bfloat16* pxb = g_preX16
                + ((size_t)(b0 + rw) * TTT + fh * 50) * HH + lane * 4;
            ull acc0 = 0, acc1 = 0;
            float zs = 0.f;
            if (t != TTT - 1) {
                const __nv_bfloat16* xeb = g_Xenc16
                    + ((size_t)(b0 + rw) * TTT + fh * 50) * HH + lane * 4;
                for (int n = 0; n < 25; n++) {
                    uint2 prA = *reinterpret_cast<const uint2*>(pxb + (2 * n) * HH);
                    uint2 prB = *reinterpret_cast<const uint2*>(pxb + (2 * n + 1) * HH);
                    uint2 xrA = *reinterpret_cast<const uint2*>(xeb + (2 * n) * HH);
                    uint2 xrB = *reinterpret_cast<const uint2*>(xeb + (2 * n + 1) * HH);
                    float2 pA0 = bf2f(prA.x), pA1 = bf2f(prA.y);
                    float2 pB0 = bf2f(prB.x), pB1 = bf2f(prB.y);
                    float sA = tanh_fast(pA0.x + uv.x) * w2v.x + tanh_fast(pA0.y + uv.y) * w2v.y
                             + tanh_fast(pA1.x + uv.z) * w2v.z + tanh_fast(pA1.y + uv.w) * w2v.w;
                    float sB = tanh_fast(pB0.x + uv.x) * w2v.x + tanh_fast(pB0.y + uv.y) * w2v.y
                             + tanh_fast(pB1.x + uv.z) * w2v.z + tanh_fast(pB1.y + uv.w) * w2v.w;
#pragma unroll
                    for (int off = 16; off; off >>= 1) {
                        sA += __shfl_xor_sync(0xffffffffu, sA, off);
                        sB += __shfl_xor_sync(0xffffffffu, sB, off);
                    }
                    float eA = __expf(sA), eB = __expf(sB);
                    zs += eA + eB;
                    ull eA2 = pack2(eA, eA), eB2 = pack2(eB, eB);
                    float2 xA0 = bf2f(xrA.x), xA1 = bf2f(xrA.y);
                    float2 xB0 = bf2f(xrB.x), xB1 = bf2f(xrB.y);
                    acc0 = ffma2(pack2(xA0.x, xA0.y), eA2, acc0);
                    acc1 = ffma2(pack2(xA1.x, xA1.y), eA2, acc1);
                    acc0 = ffma2(pack2(xB0.x, xB0.y), eB2, acc0);
                    acc1 = ffma2(pack2(xB1.x, xB1.y), eB2, acc1);
                }
            } else {
                const float* xef = g_Xenc
                    + ((size_t)(b0 + rw) * TTT + fh * 50) * HH + lane * 4;
                for (int n = 0; n < 25; n++) {
                    uint2 prA = *reinterpret_cast<const uint2*>(pxb + (2 * n) * HH);
                    uint2 prB = *reinterpret_cast<const uint2*>(pxb + (2 * n + 1) * HH);
                    float4 xfA = *reinterpret_cast<const float4*>(xef + (2 * n) * HH);
                    float4 xfB = *reinterpret_cast<const float4*>(xef + (2 * n + 1) * HH);
                    float2 pA0 = bf2f(prA.x), pA1 = bf2f(prA.y);
                    float2 pB0 = bf2f(prB.x), pB1 = bf2f(prB.y);
                    float sA = tanh_fast(pA0.x + uv.x) * w2v.x + tanh_fast(pA0.y + uv.y) * w2v.y
                             + tanh_fast(pA1.x + uv.z) * w2v.z + tanh_fast(pA1.y + uv.w) * w2v.w;
                    float sB = tanh_fast(pB0.x + uv.x) * w2v.x + tanh_fast(pB0.y + uv.y) * w2v.y
                             + tanh_fast(pB1.x + uv.z) * w2v.z + tanh_fast(pB1.y + uv.w) * w2v.w;
#pragma unroll
                    for (int off = 16; off; off >>= 1) {
                        sA += __shfl_xor_sync(0xffffffffu, sA, off);
                        sB += __shfl_xor_sync(0xffffffffu, sB, off);
                    }
                    float eA = __expf(sA), eB = __expf(sB);
                    zs += eA + eB;
                    ull eA2 = pack2(eA, eA), eB2 = pack2(eB, eB);
                    acc0 = ffma2(pack2(xfA.x, xfA.y), eA2, acc0);
                    acc1 = ffma2(pack2(xfA.z, xfA.w), eA2, acc1);
                    acc0 = ffma2(pack2(xfB.x, xfB.y), eB2, acc0);
                    acc1 = ffma2(pack2(xfB.z, xfB.w), eB2, acc1);
                }
            }
            float2 c0 = unpack2(acc0), c1 = unpack2(acc1);
            *reinterpret_cast<float4*>(&ctxp[(fh * 4 + rw) * 128 + lane * 4]) =
                make_float4(c0.x, c0.y, c1.x, c1.y);
            if (lane == 0) zbuf[fh * 4 + rw] = zs;
        } else {
            // E: gates = d @ Whh^T (fp16 gmem weights; 4 rows per thread)
            ull e00 = 0, e01 = 0, e10 = 0, e11 = 0, e20 = 0, e21 = 0, e30 = 0, e31 = 0;
            const float* dk = dcatT + (khE * 64) * 12;
#pragma unroll 4
            for (int k = 0; k < 64; k++) {
                uint2 wr = wqh[(size_t)k * 128];
                __half2 hA = *reinterpret_cast<const __half2*>(&wr.x);
                __half2 hB = *reinterpret_cast<const __half2*>(&wr.y);
                float2 wa = __half22float2(hA);
                float2 wb = __half22float2(hB);
                ulonglong2 xr = *reinterpret_cast<const ulonglong2*>(dk + k * 12);
                ull w0 = pack2(wa.x, wa.x), w1 = pack2(wa.y, wa.y);
                ull w2 = pack2(wb.x, wb.x), w3 = pack2(wb.y, wb.y);
                e00 = ffma2(xr.x, w0, e00); e01 = ffma2(xr.y, w0, e01);
                e10 = ffma2(xr.x, w1, e10); e11 = ffma2(xr.y, w1, e11);
                e20 = ffma2(xr.x, w2, e20); e21 = ffma2(xr.y, w2, e21);
                e30 = ffma2(xr.x, w3, e30); e31 = ffma2(xr.y, w3, e31);
            }
            float2 u00 = unpack2(e00), u10 = unpack2(e10), u20 = unpack2(e20), u30 = unpack2(e30);
            float2 u01 = unpack2(e01), u11 = unpack2(e11), u21 = unpack2(e21), u31 = unpack2(e31);
            float* gb = egs + (khE * 4) * 512 + g0E;
            *reinterpret_cast<float4*>(gb + 0 * 512) = make_float4(u00.x, u10.x, u20.x, u30.x);
            *reinterpret_cast<float4*>(gb + 1 * 512) = make_float4(u00.y, u10.y, u20.y, u30.y);
            *reinterpret_cast<float4*>(gb + 2 * 512) = make_float4(u01.x, u11.x, u21.x, u31.x);
            *reinterpret_cast<float4*>(gb + 3 * 512) = make_float4(u01.y, u11.y, u21.y, u31.y);
        }
        __syncthreads();

        // ---- ctx combine + y (warps 0-3, one row each)
        if (wp < 4) {
            float4 p0 = *reinterpret_cast<const float4*>(&ctxp[wp * 128 + lane * 4]);
            float4 p1 = *reinterpret_cast<const float4*>(&ctxp[512 + wp * 128 + lane * 4]);
            float rz = __fdividef(1.f, zbuf[wp] + zbuf[4 + wp]);
            float4 cx = make_float4((p0.x + p1.x) * rz, (p0.y + p1.y) * rz,
                                    (p0.z + p1.z) * rz, (p0.w + p1.w) * rz);
            *reinterpret_cast<float4*>(&ctx_s[wp * 128 + lane * 4]) = cx;
            float s = cx.x * fwv.x + cx.y * fwv.y + cx.z * fwv.z + cx.w * fwv.w;
#pragma unroll
            for (int off = 16; off; off >>= 1) s += __shfl_xor_sync(0xffffffffu, s, off);
            if (lane == 0) y_s[wp] = s + fcb;
        }
        __syncthreads();
        // ---- F: state update for (r, jr)
        {
            float yv = y_s[r];
            float iv = egs[(0 + r) * 512 + jr      ] + egs[(4 + r) * 512 + jr      ] + yv * wih4[0] + bia4[0];
            float fv = egs[(0 + r) * 512 + jr + 128] + egs[(4 + r) * 512 + jr + 128] + yv * wih4[1] + bia4[1];
            float gv = egs[(0 + r) * 512 + jr + 256] + egs[(4 + r) * 512 + jr + 256] + yv * wih4[2] + bia4[2];
            float ov = egs[(0 + r) * 512 + jr + 384] + egs[(4 + r) * 512 + jr + 384] + yv * wih4[3] + bia4[3];
            float cn = sigm(fv) * c_reg + sigm(iv) * tanh_s(gv);
            float hn = sigm(ov) * tanh_s(cn);
            c_reg = cn;
            dcatT[jr * 12 + r] = hn;
            dcatT[(128 + jr) * 12 + r] = cn;
        }
        __syncthreads();
    }
    // ---- final FC: out = [d, ctx] @ fcfW^T + fcfb (stage fcfW into W1dc region)
    {
        float* Wf = sm;     // reuse W1dc slots (16384 floats >= 32*257)
        for (int i = tid; i < CC * 256; i += 512) {
            int cl = i >> 8, k = i & 255;
            Wf[cl * 257 + k] = fcfW[i];
        }
        __syncthreads();
        if (tid < 128) {
            int cl = tid & 31, rl = tid >> 5;
            float a = fcfB[cl];
#pragma unroll 8
            for (int k = 0; k < 128; k++) a += dcatT[k * 12 + rl] * Wf[cl * 257 + k];
#pragma unroll 8
            for (int k = 0; k < 128; k++) a += ctx_s[rl * 128 + k] * Wf[cl * 257 + 128 + k];
            out[(b0 + rl) * CC + cl] = a;
        }
    }
}

// ---------------- host launcher ----------------
extern "C" void kernel_launch(void* const* d_in, const int* in_sizes, int n_in,
                              void* d_out, int out_size) {
    (void)in_sizes; (void)n_in; (void)out_size;
    const float* X       = (const float*)d_in[0];
    const float* encWih  = (const float*)d_in[1];
    const float* encWhh  = (const float*)d_in[2];
    const float* encBih  = (const float*)d_in[3];
    const float* encBhh  = (const float*)d_in[4];
    const float* encAttW = (const float*)d_in[5];
    const float* decW1   = (const float*)d_in[7];
    const float* decB1   = (const float*)d_in[8];
    const float* decW2   = (const float*)d_in[9];
    const float* decWih  = (const float*)d_in[11];
    const float* decWhh  = (const float*)d_in[12];
    const float* decBih  = (const float*)d_in[13];
    const float* decBhh  = (const float*)d_in[14];
    const float* fcW     = (const float*)d_in[15];
    const float* fcB     = (const float*)d_in[16];
    const float* fcfW    = (const float*)d_in[17];
    const float* fcfB    = (const float*)d_in[18];
    float* out = (float*)d_out;

    cudaFuncSetAttribute(gemm_g1, cudaFuncAttributeMaxDynamicSharedMemorySize,
                         G1_SMEM_BYTES);
    cudaFuncSetAttribute(enc_fused, cudaFuncAttributeMaxDynamicSharedMemorySize,
                         ENC_SMEM_FLOATS * 4);
    cudaFuncSetAttribute(dec_fused, cudaFuncAttributeMaxDynamicSharedMemorySize,
                         DEC_SMEM_FLOATS * 4);

    prep_alpha<<<964 + BB / 2, 256>>>(X, encAttW, encWih, encWhh, decWhh, decW1,
                                      encBih, encBhh, decBih, decBhh);
    gemm_g1<<<BB * TTT / 128, 256, G1_SMEM_BYTES>>>();
    enc_fused<<<BB / 8, 1024, ENC_SMEM_FLOATS * 4>>>();
    gemm_preX16<<<BB * TTT / 128, 256, PREX_SMEM_BYTES>>>(decB1);
    dec_fused<<<BB / 4, 512, DEC_SMEM_FLOATS * 4>>>(decWih, decW2, fcW, fcB, fcfW, fcfB, out);
}

// round 17
// speedup vs baseline: 1.0408x; 1.0408x over previous
#include <cuda_runtime.h>
#include <cuda_bf16.h>
#include <cuda_fp16.h>
#include <cstdint>

#define BB 1024
#define TTT 100
#define MM 128
#define HH 128
#define PP 128
#define CC 32
#define GG 512

// ---------------- device scratch ----------------
__device__ __half g_x16[(size_t)BB * TTT * MM];             // fp16 x_tilde
__device__ __half g_G1h[(size_t)BB * TTT * GG];             // fp16 x_tilde@Wih^T
__device__ float g_Xenc[(size_t)BB * TTT * HH];
__device__ __nv_bfloat16 g_Xenc16[(size_t)BB * TTT * HH];
__device__ __nv_bfloat16 g_preX16[(size_t)BB * TTT * HH];
__device__ __half g_encWhh16[128 * GG];                     // [k][g]
__device__ __half g_decWhh16[128 * GG];                     // [k][g]
__device__ __half g_Wih16[GG * MM];                         // [g][k]
__device__ __nv_bfloat16 g_W1x16[128 * 128];                // [h][k] bf16
__device__ float g_W1dcT[256 * HH];                         // [k][h] fp32
__device__ float g_encBias[GG];
__device__ float g_decBias[GG];

typedef unsigned long long ull;

__device__ __forceinline__ ull pack2(float x, float y) {
    ull r;
    asm("mov.b64 %0, {%1, %2};" : "=l"(r)
        : "r"(__float_as_uint(x)), "r"(__float_as_uint(y)));
    return r;
}
__device__ __forceinline__ float2 unpack2(ull v) {
    unsigned int lo, hi;
    asm("mov.b64 {%0, %1}, %2;" : "=r"(lo), "=r"(hi) : "l"(v));
    return make_float2(__uint_as_float(lo), __uint_as_float(hi));
}
__device__ __forceinline__ ull ffma2(ull a, ull b, ull c) {
    ull d;
    asm("fma.rn.f32x2 %0, %1, %2, %3;" : "=l"(d) : "l"(a), "l"(b), "l"(c));
    return d;
}
__device__ __forceinline__ float sigm(float x) {
    return 1.0f / (1.0f + __expf(-x));
}
__device__ __forceinline__ float tanh_s(float x) {
    float a = fabsf(x);
    float e = __expf(-2.0f * a);
    float r = (1.0f - e) / (1.0f + e);
    return copysignf(r, x);
}
__device__ __forceinline__ float tanh_fast(float x) {
    float y;
    asm("tanh.approx.f32 %0, %1;" : "=f"(y) : "f"(x));
    return y;
}
__device__ __forceinline__ float2 bf2f(unsigned int u) {
    __nv_bfloat162 h = *reinterpret_cast<__nv_bfloat162*>(&u);
    return __bfloat1622float2(h);
}

// ---------------- merged prep + alpha/x16 ----------------
__global__ void prep_alpha(const float* __restrict__ X, const float* __restrict__ Wa,
                           const float* __restrict__ encWih, const float* __restrict__ encWhh,
                           const float* __restrict__ decWhh, const float* __restrict__ decW1,
                           const float* __restrict__ ebih, const float* __restrict__ ebhh,
                           const float* __restrict__ dbih, const float* __restrict__ dbhh) {
    int blk = blockIdx.x, tid = threadIdx.x;
    if (blk < 964) {
        int idx = blk * 256 + tid;
        if (idx < 65536) {
            int k = idx >> 9, gg = idx & 511;
            g_encWhh16[idx] = __float2half(encWhh[gg * 128 + k]);
        } else if (idx < 131072) {
            int l = idx - 65536; int k = l >> 9, gg = l & 511;
            g_decWhh16[l] = __float2half(decWhh[gg * 128 + k]);
        } else if (idx < 196608) {
            int l = idx - 131072;
            g_Wih16[l] = __float2half(encWih[l]);
        } else if (idx < 229376) {
            int l = idx - 196608; int hh = l & 127, k = l >> 7;
            g_W1dcT[l] = decW1[hh * 384 + k];
        } else if (idx < 245760) {
            int l = idx - 229376; int hh = l >> 7, k = l & 127;   // [h][k]
            g_W1x16[l] = __float2bfloat16(decW1[hh * 384 + 256 + k]);
        } else if (idx < 246272) {
            int gg = idx - 245760; g_encBias[gg] = ebih[gg] + ebhh[gg];
        } else if (idx < 246784) {
            int gg = idx - 246272; g_decBias[gg] = dbih[gg] + dbhh[gg];
        }
    } else {
        __shared__ float wa[TTT];
        __shared__ float buf[2][128];
        int hf = tid >> 7, m = tid & 127;
        int b = (blk - 964) * 2 + hf;
        if (tid < TTT) wa[tid] = Wa[2 * HH + tid];
        __syncthreads();
        const float* xb = X + (size_t)b * TTT * MM + m;
        float a0 = 0.f, a1 = 0.f, a2 = 0.f, a3 = 0.f;
#pragma unroll
        for (int tt = 0; tt < TTT / 4; tt++) {
            a0 += xb[(tt * 4 + 0) * MM] * wa[tt * 4 + 0];
            a1 += xb[(tt * 4 + 1) * MM] * wa[tt * 4 + 1];
            a2 += xb[(tt * 4 + 2) * MM] * wa[tt * 4 + 2];
            a3 += xb[(tt * 4 + 3) * MM] * wa[tt * 4 + 3];
        }
        float s = (a0 + a1) + (a2 + a3);
        buf[hf][m] = s; __syncthreads();
        for (int st = 64; st > 0; st >>= 1) {
            if (m < st) buf[hf][m] = fmaxf(buf[hf][m], buf[hf][m + st]);
            __syncthreads();
        }
        float mx = buf[hf][0]; __syncthreads();
        float e = __expf(s - mx);
        buf[hf][m] = e; __syncthreads();
        for (int st = 64; st > 0; st >>= 1) {
            if (m < st) buf[hf][m] += buf[hf][m + st];
            __syncthreads();
        }
        float alpha = e / buf[hf][0];
        __half* xo = g_x16 + (size_t)b * TTT * MM + m;
#pragma unroll 4
        for (int t = 0; t < TTT; t++)
            xo[t * MM] = __float2half(xb[t * MM] * alpha);
    }
}

// ---------------- G1 = x16 @ Wih16^T via mma.sync m16n8k16 ----------------
#define G1_SMEM_BYTES (512 * 136 * 2)
__global__ __launch_bounds__(256) void gemm_g1() {
    extern __shared__ __half Bs[];      // [512][136]
    int tid = threadIdx.x, wid = tid >> 5, lane = tid & 31;
    {
        const unsigned int* src = reinterpret_cast<const unsigned int*>(g_Wih16);
        for (int i = tid; i < 32768; i += 256) {
            int n = i >> 6, kk = i & 63;
            *(reinterpret_cast<unsigned int*>(Bs + n * 136) + kk) = src[i];
        }
    }
    __syncthreads();
    int m0 = blockIdx.x * 128 + wid * 16;
    int grp = lane >> 2, tig = lane & 3;
    const __half* a0p = g_x16 + (size_t)m0 * 128 + (size_t)grp * 128 + tig * 2;

    for (int nc = 0; nc < 8; nc++) {
        float c[8][4];
#pragma unroll
        for (int nt = 0; nt < 8; nt++) {
            c[nt][0] = 0.f; c[nt][1] = 0.f; c[nt][2] = 0.f; c[nt][3] = 0.f;
        }
#pragma unroll
        for (int ks = 0; ks < 8; ks++) {
            unsigned int a0 = *reinterpret_cast<const unsigned int*>(a0p + ks * 16);
            unsigned int a1 = *reinterpret_cast<const unsigned int*>(a0p + 8 * 128 + ks * 16);
            unsigned int a2 = *reinterpret_cast<const unsigned int*>(a0p + ks * 16 + 8);
            unsigned int a3 = *reinterpret_cast<const unsigned int*>(a0p + 8 * 128 + ks * 16 + 8);
#pragma unroll
            for (int nt = 0; nt < 8; nt++) {
                int n = nc * 64 + nt * 8 + grp;
                const __half* bp = Bs + n * 136 + ks * 16 + tig * 2;
                unsigned int b0 = *reinterpret_cast<const unsigned int*>(bp);
                unsigned int b1 = *reinterpret_cast<const unsigned int*>(bp + 8);
                asm volatile(
                    "mma.sync.aligned.m16n8k16.row.col.f32.f16.f16.f32 "
                    "{%0,%1,%2,%3}, {%4,%5,%6,%7}, {%8,%9}, {%0,%1,%2,%3};"
                    : "+f"(c[nt][0]), "+f"(c[nt][1]), "+f"(c[nt][2]), "+f"(c[nt][3])
                    : "r"(a0), "r"(a1), "r"(a2), "r"(a3), "r"(b0), "r"(b1));
            }
        }
#pragma unroll
        for (int nt = 0; nt < 8; nt++) {
            int col = nc * 64 + nt * 8 + tig * 2;
            __half2 lo = __floats2half2_rn(c[nt][0], c[nt][1]);
            __half2 hi = __floats2half2_rn(c[nt][2], c[nt][3]);
            *reinterpret_cast<__half2*>(g_G1h + (size_t)(m0 + grp) * 512 + col) = lo;
            *reinterpret_cast<__half2*>(g_G1h + (size_t)(m0 + grp + 8) * 512 + col) = hi;
        }
    }
}

// ---------------- preX = Xenc16 @ W1x^T + b1 -> bf16 via bf16 mma ----------------
#define PREX_SMEM_BYTES (128 * 136 * 2)
__global__ __launch_bounds__(256) void gemm_preX16(const float* __restrict__ b1) {
    extern __shared__ __nv_bfloat16 Bx[];   // [128][136]
    __shared__ float b1s[128];
    int tid = threadIdx.x, wid = tid >> 5, lane = tid & 31;
    {
        const unsigned int* src = reinterpret_cast<const unsigned int*>(g_W1x16);
        for (int i = tid; i < 8192; i += 256) {
            int n = i >> 6, kk = i & 63;
            *(reinterpret_cast<unsigned int*>(Bx + n * 136) + kk) = src[i];
        }
        if (tid < 128) b1s[tid] = b1[tid];
    }
    __syncthreads();
    int m0 = blockIdx.x * 128 + wid * 16;
    int grp = lane >> 2, tig = lane & 3;
    const __nv_bfloat16* a0p = g_Xenc16 + (size_t)m0 * 128 + (size_t)grp * 128 + tig * 2;

    for (int nc = 0; nc < 2; nc++) {
        float c[8][4];
#pragma unroll
        for (int nt = 0; nt < 8; nt++) {
            c[nt][0] = 0.f; c[nt][1] = 0.f; c[nt][2] = 0.f; c[nt][3] = 0.f;
        }
#pragma unroll
        for (int ks = 0; ks < 8; ks++) {
            unsigned int a0 = *reinterpret_cast<const unsigned int*>(a0p + ks * 16);
            unsigned int a1 = *reinterpret_cast<const unsigned int*>(a0p + 8 * 128 + ks * 16);
            unsigned int a2 = *reinterpret_cast<const unsigned int*>(a0p + ks * 16 + 8);
            unsigned int a3 = *reinterpret_cast<const unsigned int*>(a0p + 8 * 128 + ks * 16 + 8);
#pragma unroll
            for (int nt = 0; nt < 8; nt++) {
                int n = nc * 64 + nt * 8 + grp;
                const __nv_bfloat16* bp = Bx + n * 136 + ks * 16 + tig * 2;
                unsigned int b0 = *reinterpret_cast<const unsigned int*>(bp);
                unsigned int bq = *reinterpret_cast<const unsigned int*>(bp + 8);
                asm volatile(
                    "mma.sync.aligned.m16n8k16.row.col.f32.bf16.bf16.f32 "
                    "{%0,%1,%2,%3}, {%4,%5,%6,%7}, {%8,%9}, {%0,%1,%2,%3};"
                    : "+f"(c[nt][0]), "+f"(c[nt][1]), "+f"(c[nt][2]), "+f"(c[nt][3])
                    : "r"(a0), "r"(a1), "r"(a2), "r"(a3), "r"(b0), "r"(bq));
            }
        }
#pragma unroll
        for (int nt = 0; nt < 8; nt++) {
            int col = nc * 64 + nt * 8 + tig * 2;
            float bl = b1s[col], bh = b1s[col + 1];
            __nv_bfloat162 lo = __floats2bfloat162_rn(c[nt][0] + bl, c[nt][1] + bh);
            __nv_bfloat162 hi = __floats2bfloat162_rn(c[nt][2] + bl, c[nt][3] + bh);
            *reinterpret_cast<__nv_bfloat162*>(g_preX16 + (size_t)(m0 + grp) * 128 + col) = lo;
            *reinterpret_cast<__nv_bfloat162*>(g_preX16 + (size_t)(m0 + grp + 8) * 128 + col) = hi;
        }
    }
}

// ---------------- fused encoder: K=128 recurrence, fp16 Whh, 2 syncs/step ----------
#define ENC_SMEM_FLOATS (1536 + 16384)
__global__ __launch_bounds__(1024, 1) void enc_fused() {
    extern __shared__ float es[];
    float* hT  = es;            // [128][12]
    float* gsb = es + 1536;     // [4][8][512]
    const int b0 = blockIdx.x * 8;
    const int tid = threadIdx.x;
    const int gq = tid & 127, rh = (tid >> 7) & 1, kq = tid >> 8;
    const int g0 = gq * 4, rb = rh * 4;
    const int jr = tid & 127, r = tid >> 7;
    float bia4[4];
#pragma unroll
    for (int x = 0; x < 4; x++) bia4[x] = g_encBias[jr + 128 * x];
    float c_reg = 0.f;
    hT[jr * 12 + r] = 0.f;
    const size_t xrow = (size_t)(b0 + r) * TTT;
    const uint2* wq = reinterpret_cast<const uint2*>(g_encWhh16)
                      + (size_t)(kq * 32) * 128 + gq;
    const __half* g1p = g_G1h + xrow * 512 + jr;
    __syncthreads();

    for (int t = 0; t < TTT; t++) {
        ull a00 = 0, a01 = 0, a10 = 0, a11 = 0, a20 = 0, a21 = 0, a30 = 0, a31 = 0;
        const float* xp = hT + (kq * 32) * 12 + rb;
#pragma unroll 4
        for (int k = 0; k < 32; k++) {
            uint2 wr = wq[(size_t)k * 128];
            __half2 hA = *reinterpret_cast<const __half2*>(&wr.x);
            __half2 hB = *reinterpret_cast<const __half2*>(&wr.y);
            float2 wa = __half22float2(hA);
            float2 wb = __half22float2(hB);
            ulonglong2 xr = *reinterpret_cast<const ulonglong2*>(xp + k * 12);
            ull w0 = pack2(wa.x, wa.x), w1 = pack2(wa.y, wa.y);
            ull w2 = pack2(wb.x, wb.x), w3 = pack2(wb.y, wb.y);
            a00 = ffma2(xr.x, w0, a00); a01 = ffma2(xr.y, w0, a01);
            a10 = ffma2(xr.x, w1, a10); a11 = ffma2(xr.y, w1, a11);
            a20 = ffma2(xr.x, w2, a20); a21 = ffma2(xr.y, w2, a21);
            a30 = ffma2(xr.x, w3, a30); a31 = ffma2(xr.y, w3, a31);
        }
        {
            float2 u00 = unpack2(a00), u10 = unpack2(a10), u20 = unpack2(a20), u30 = unpack2(a30);
            float2 u01 = unpack2(a01), u11 = unpack2(a11), u21 = unpack2(a21), u31 = unpack2(a31);
            float* gb = gsb + (kq * 8 + rb) * 512 + g0;
            *reinterpret_cast<float4*>(gb + 0 * 512) = make_float4(u00.x, u10.x, u20.x, u30.x);
            *reinterpret_cast<float4*>(gb + 1 * 512) = make_float4(u00.y, u10.y, u20.y, u30.y);
            *reinterpret_cast<float4*>(gb + 2 * 512) = make_float4(u01.x, u11.x, u21.x, u31.x);
            *reinterpret_cast<float4*>(gb + 3 * 512) = make_float4(u01.y, u11.y, u21.y, u31.y);
        }
        __syncthreads();
        const __half* gp = g1p + (size_t)t * 512;
        float iv = gsb[(0 + r) * 512 + jr      ] + gsb[(8 + r) * 512 + jr      ]
                 + gsb[(16 + r) * 512 + jr     ] + gsb[(24 + r) * 512 + jr     ]
                 + __half2float(gp[0])   + bia4[0];
        float fv = gsb[(0 + r) * 512 + jr + 128] + gsb[(8 + r) * 512 + jr + 128]
                 + gsb[(16 + r) * 512 + jr + 128] + gsb[(24 + r) * 512 + jr + 128]
                 + __half2float(gp[128]) + bia4[1];
        float gv = gsb[(0 + r) * 512 + jr + 256] + gsb[(8 + r) * 512 + jr + 256]
                 + gsb[(16 + r) * 512 + jr + 256] + gsb[(24 + r) * 512 + jr + 256]
                 + __half2float(gp[256]) + bia4[2];
        float ov = gsb[(0 + r) * 512 + jr + 384] + gsb[(8 + r) * 512 + jr + 384]
                 + gsb[(16 + r) * 512 + jr + 384] + gsb[(24 + r) * 512 + jr + 384]
                 + __half2float(gp[384]) + bia4[3];
        float cn = sigm(fv) * c_reg + sigm(iv) * tanh_s(gv);
        float hn = sigm(ov) * tanh_s(cn);
        c_reg = cn;
        // safe: all hT reads for step t completed before the gsb barrier above
        hT[jr * 12 + r] = hn;
        g_Xenc[(xrow + t) * HH + jr] = hn;
        g_Xenc16[(xrow + t) * HH + jr] = __float2bfloat16(hn);
        __syncthreads();
    }
}

// ---------------- fused decoder: R15 base + half-warp B-phase ----------------
#define DEC_SMEM_FLOATS (32768 + 3072 + 8192 + 1024 + 1024 + 2048 + 16 + 8 + 128 + 128)

__global__ __launch_bounds__(1024, 1) void dec_fused(
    const float* __restrict__ decWih, const float* __restrict__ decW2,
    const float* __restrict__ fcW, const float* __restrict__ fcB,
    const float* __restrict__ fcfW, const float* __restrict__ fcfB,
    float* __restrict__ out)
{
    extern __shared__ float sm[];
    float* W1dcS = sm;
    float* dcatT = sm + 32768;
    float* gsb   = dcatT + 3072;
    float* u_s   = gsb + 8192;
    float* ctx_s = u_s + 1024;
    float* ctxp  = ctx_s + 1024;
    float* zbuf  = ctxp + 2048;
    float* y_s   = zbuf + 16;
    float* w2_s  = y_s + 8;
    float* fw_s  = w2_s + 128;

    const int b0 = blockIdx.x * 8;
    const int tid = threadIdx.x;
    const int lane = tid & 31, wp = tid >> 5;
    const int jr = tid & 127;
    const int r  = tid >> 7;

    for (int i = tid; i < 32768; i += 1024) W1dcS[i] = g_W1dcT[i];
    for (int i = tid; i < 3072; i += 1024) dcatT[i] = 0.f;
    if (tid < 128) { w2_s[tid] = decW2[tid]; fw_s[tid] = fcW[tid]; }
    float wih4[4], bia4[4];
#pragma unroll
    for (int x = 0; x < 4; x++) {
        wih4[x] = decWih[jr + 128 * x];
        bia4[x] = g_decBias[jr + 128 * x];
    }
    float c_reg = 0.f;
    const float fcb = fcB[0];
    const int ti = tid - 512;
    const int gqE = ti & 127, rhE = (ti >> 7) & 1, khE = (tid >= 512) ? (ti >> 8) : 0;
    const int g0E = gqE * 4, rbE = rhE * 4;
    const uint2* wqh = reinterpret_cast<const uint2*>(g_decWhh16)
                       + (size_t)(khE * 64) * 128 + gqE;
    // B-phase half-warp mapping
    const int half = lane >> 4, hl = lane & 15;
    __syncthreads();
    const float4 fwv = *reinterpret_cast<const float4*>(&fw_s[lane * 4]);
    // w2 for this lane's 8 h-channels
    const float4 w2a = *reinterpret_cast<const float4*>(&w2_s[hl * 8]);
    const float4 w2b = *reinterpret_cast<const float4*>(&w2_s[hl * 8 + 4]);

    for (int t = 0; t < TTT; t++) {
        // A: u = [d;cc] @ W1dc^T
        {
            ull a0 = 0, a1 = 0, a2 = 0, a3 = 0;
            const float* wA = W1dcS + (r * 32) * 128 + jr;
            const float* dk = dcatT + (r * 32) * 12;
#pragma unroll 4
            for (int kk = 0; kk < 32; kk++) {
                float w = wA[kk * 128];
                ull ww = pack2(w, w);
                ulonglong2 p0 = *reinterpret_cast<const ulonglong2*>(dk + kk * 12);
                ulonglong2 p1 = *reinterpret_cast<const ulonglong2*>(dk + kk * 12 + 4);
                a0 = ffma2(p0.x, ww, a0);
                a1 = ffma2(p0.y, ww, a1);
                a2 = ffma2(p1.x, ww, a2);
                a3 = ffma2(p1.y, ww, a3);
            }
            float2 f;
            f = unpack2(a0); gsb[(r * 8 + 0) * 128 + jr] = f.x; gsb[(r * 8 + 1) * 128 + jr] = f.y;
            f = unpack2(a1); gsb[(r * 8 + 2) * 128 + jr] = f.x; gsb[(r * 8 + 3) * 128 + jr] = f.y;
            f = unpack2(a2); gsb[(r * 8 + 4) * 128 + jr] = f.x; gsb[(r * 8 + 5) * 128 + jr] = f.y;
            f = unpack2(a3); gsb[(r * 8 + 6) * 128 + jr] = f.x; gsb[(r * 8 + 7) * 128 + jr] = f.y;
        }
        __syncthreads();
        {
            float u = 0.f;
#pragma unroll
            for (int qq = 0; qq < 8; qq++) u += gsb[(qq * 8 + r) * 128 + jr];
            u_s[r * 128 + jr] = u;
        }
        __syncthreads();

        // parallel: B (half-warp per item) warps 0-15 | E warps 16-31
        if (tid < 512) {
            const int rw = wp & 7, fh = wp >> 3;
            // u for this lane's 8 h
            float4 u0 = *reinterpret_cast<const float4*>(&u_s[rw * 128 + hl * 8]);
            float4 u1 = *reinterpret_cast<const float4*>(&u_s[rw * 128 + hl * 8 + 4]);
            const __nv_bfloat16* pxb = g_preX16
                + ((size_t)(b0 + rw) * TTT + fh * 50 + half) * HH + hl * 8;
            ull acc0 = 0, acc1 = 0, acc2 = 0, acc3 = 0;
            float zs = 0.f;
            if (t != TTT - 1) {
                const __nv_bfloat16* xeb = g_Xenc16
                    + ((size_t)(b0 + rw) * TTT + fh * 50 + half) * HH + hl * 8;
                for (int n = 0; n < 25; n++) {
                    uint4 pr = *reinterpret_cast<const uint4*>(pxb + (2 * n) * HH);
                    uint4 xr = *reinterpret_cast<const uint4*>(xeb + (2 * n) * HH);
                    float2 p0 = bf2f(pr.x), p1 = bf2f(pr.y), p2 = bf2f(pr.z), p3 = bf2f(pr.w);
                    float s = tanh_fast(p0.x + u0.x) * w2a.x + tanh_fast(p0.y + u0.y) * w2a.y
                            + tanh_fast(p1.x + u0.z) * w2a.z + tanh_fast(p1.y + u0.w) * w2a.w
                            + tanh_fast(p2.x + u1.x) * w2b.x + tanh_fast(p2.y + u1.y) * w2b.y
                            + tanh_fast(p3.x + u1.z) * w2b.z + tanh_fast(p3.y + u1.w) * w2b.w;
#pragma unroll
                    for (int off = 8; off; off >>= 1)
                        s += __shfl_xor_sync(0xffffffffu, s, off);
                    float e = __expf(s);
                    zs += e;
                    ull e2 = pack2(e, e);
                    float2 x0 = bf2f(xr.x), x1 = bf2f(xr.y), x2 = bf2f(xr.z), x3 = bf2f(xr.w);
                    acc0 = ffma2(pack2(x0.x, x0.y), e2, acc0);
                    acc1 = ffma2(pack2(x1.x, x1.y), e2, acc1);
                    acc2 = ffma2(pack2(x2.x, x2.y), e2, acc2);
                    acc3 = ffma2(pack2(x3.x, x3.y), e2, acc3);
                }
            } else {
                const float* xef = g_Xenc
                    + ((size_t)(b0 + rw) * TTT + fh * 50 + half) * HH + hl * 8;
                for (int n = 0; n < 25; n++) {
                    uint4 pr = *reinterpret_cast<const uint4*>(pxb + (2 * n) * HH);
                    float4 xf0 = *reinterpret_cast<const float4*>(xef + (2 * n) * HH);
                    float4 xf1 = *reinterpret_cast<const float4*>(xef + (2 * n) * HH + 4);
                    float2 p0 = bf2f(pr.x), p1 = bf2f(pr.y), p2 = bf2f(pr.z), p3 = bf2f(pr.w);
                    float s = tanh_fast(p0.x + u0.x) * w2a.x + tanh_fast(p0.y + u0.y) * w2a.y
                            + tanh_fast(p1.x + u0.z) * w2a.z + tanh_fast(p1.y + u0.w) * w2a.w
                            + tanh_fast(p2.x + u1.x) * w2b.x + tanh_fast(p2.y + u1.y) * w2b.y
                            + tanh_fast(p3.x + u1.z) * w2b.z + tanh_fast(p3.y + u1.w) * w2b.w;
#pragma unroll
                    for (int off = 8; off; off >>= 1)
                        s += __shfl_xor_sync(0xffffffffu, s, off);
                    float e = __expf(s);
                    zs += e;
                    ull e2 = pack2(e, e);
                    acc0 = ffma2(pack2(xf0.x, xf0.y), e2, acc0);
                    acc1 = ffma2(pack2(xf0.z, xf0.w), e2, acc1);
                    acc2 = ffma2(pack2(xf1.x, xf1.y), e2, acc2);
                    acc3 = ffma2(pack2(xf1.z, xf1.w), e2, acc3);
                }
            }
            // combine halves (items 2n vs 2n+1): ctx partials and z
            zs += __shfl_xor_sync(0xffffffffu, zs, 16);
            ull o0 = __shfl_xor_sync(0xffffffffu, acc0, 16);
            ull o1 = __shfl_xor_sync(0xffffffffu, acc1, 16);
            ull o2 = __shfl_xor_sync(0xffffffffu, acc2, 16);
            ull o3 = __shfl_xor_sync(0xffffffffu, acc3, 16);
            if (half == 0) {
                float2 a0 = unpack2(acc0), b0v = unpack2(o0);
                float2 a1 = unpack2(acc1), b1v = unpack2(o1);
                float2 a2 = unpack2(acc2), b2v = unpack2(o2);
                float2 a3 = unpack2(acc3), b3v = unpack2(o3);
                float* cp = &ctxp[(fh * 8 + rw) * 128 + hl * 8];
                *reinterpret_cast<float4*>(cp) =
                    make_float4(a0.x + b0v.x, a0.y + b0v.y, a1.x + b1v.x, a1.y + b1v.y);
                *reinterpret_cast<float4*>(cp + 4) =
                    make_float4(a2.x + b2v.x, a2.y + b2v.y, a3.x + b3v.x, a3.y + b3v.y);
                if (hl == 0) zbuf[fh * 8 + rw] = zs;
            }
        } else {
            ull e00 = 0, e01 = 0, e10 = 0, e11 = 0, e20 = 0, e21 = 0, e30 = 0, e31 = 0;
            const float* dk = dcatT + (khE * 64) * 12 + rbE;
#pragma unroll 4
            for (int k = 0; k < 64; k++) {
                uint2 wr = wqh[(size_t)k * 128];
                __half2 hA = *reinterpret_cast<const __half2*>(&wr.x);
                __half2 hB = *reinterpret_cast<const __half2*>(&wr.y);
                float2 wa = __half22float2(hA);
                float2 wb = __half22float2(hB);
                ulonglong2 xr = *reinterpret_cast<const ulonglong2*>(dk + k * 12);
                ull w0 = pack2(wa.x, wa.x), w1 = pack2(wa.y, wa.y);
                ull w2 = pack2(wb.x, wb.x), w3 = pack2(wb.y, wb.y);
                e00 = ffma2(xr.x, w0, e00); e01 = ffma2(xr.y, w0, e01);
                e10 = ffma2(xr.x, w1, e10); e11 = ffma2(xr.y, w1, e11);
                e20 = ffma2(xr.x, w2, e20); e21 = ffma2(xr.y, w2, e21);
                e30 = ffma2(xr.x, w3, e30); e31 = ffma2(xr.y, w3, e31);
            }
            float2 u00 = unpack2(e00), u10 = unpack2(e10), u20 = unpack2(e20), u30 = unpack2(e30);
            float2 u01 = unpack2(e01), u11 = unpack2(e11), u21 = unpack2(e21), u31 = unpack2(e31);
            float* gb = gsb + (khE * 8 + rbE) * 512 + g0E;
            *reinterpret_cast<float4*>(gb + 0 * 512) = make_float4(u00.x, u10.x, u20.x, u30.x);
            *reinterpret_cast<float4*>(gb + 1 * 512) = make_float4(u00.y, u10.y, u20.y, u30.y);
            *reinterpret_cast<float4*>(gb + 2 * 512) = make_float4(u01.x, u11.x, u21.x, u31.x);
            *reinterpret_cast<float4*>(gb + 3 * 512) = make_float4(u01.y, u11.y, u21.y, u31.y);
        }
        __syncthreads();

        if (wp < 8) {
            float4 p0 = *reinterpret_cast<const float4*>(&ctxp[wp * 128 + lane * 4]);
            float4 p1 = *reinterpret_cast<const float4*>(&ctxp[1024 + wp * 128 + lane * 4]);
            float rz = __fdividef(1.f, zbuf[wp] + zbuf[8 + wp]);
            float4 cx = make_float4((p0.x + p1.x) * rz, (p0.y + p1.y) * rz,
                                    (p0.z + p1.z) * rz, (p0.w + p1.w) * rz);
            *reinterpret_cast<float4*>(&ctx_s[wp * 128 + lane * 4]) = cx;
            float s = cx.x * fwv.x + cx.y * fwv.y + cx.z * fwv.z + cx.w * fwv.w;
#pragma unroll
            for (int off = 16; off; off >>= 1) s += __shfl_xor_sync(0xffffffffu, s, off);
            if (lane == 0) y_s[wp] = s + fcb;
        }
        __syncthreads();
        {
            float yv = y_s[r];
            float iv = gsb[(0 + r) * 512 + jr      ] + gsb[(8 + r) * 512 + jr      ] + yv * wih4[0] + bia4[0];
            float fv = gsb[(0 + r) * 512 + jr + 128] + gsb[(8 + r) * 512 + jr + 128] + yv * wih4[1] + bia4[1];
            float gv = gsb[(0 + r) * 512 + jr + 256] + gsb[(8 + r) * 512 + jr + 256] + yv * wih4[2] + bia4[2];
            float ov = gsb[(0 + r) * 512 + jr + 384] + gsb[(8 + r) * 512 + jr + 384] + yv * wih4[3] + bia4[3];
            float cn = sigm(fv) * c_reg + sigm(iv) * tanh_s(gv);
            float hn = sigm(ov) * tanh_s(cn);
            c_reg = cn;
            dcatT[jr * 12 + r] = hn;
            dcatT[(128 + jr) * 12 + r] = cn;
        }
        __syncthreads();
    }
    for (int i = tid; i < CC * 256; i += 1024) {
        int cl = i >> 8, k = i & 255;
        W1dcS[cl * 257 + k] = fcfW[i];
    }
    __syncthreads();
    if (tid < 256) {
        int cl = tid & 31, rl = tid >> 5;
        float a = fcfB[cl];
#pragma unroll 8
        for (int k = 0; k < 128; k++) a += dcatT[k * 12 + rl] * W1dcS[cl * 257 + k];
#pragma unroll 8
        for (int k = 0; k < 128; k++) a += ctx_s[rl * 128 + k] * W1dcS[cl * 257 + 128 + k];
        out[(b0 + rl) * CC + cl] = a;
    }
}

// ---------------- host launcher ----------------
extern "C" void kernel_launch(void* const* d_in, const int* in_sizes, int n_in,
                              void* d_out, int out_size) {
    (void)in_sizes; (void)n_in; (void)out_size;
    const float* X       = (const float*)d_in[0];
    const float* encWih  = (const float*)d_in[1];
    const float* encWhh  = (const float*)d_in[2];
    const float* encBih  = (const float*)d_in[3];
    const float* encBhh  = (const float*)d_in[4];
    const float* encAttW = (const float*)d_in[5];
    const float* decW1   = (const float*)d_in[7];
    const float* decB1   = (const float*)d_in[8];
    const float* decW2   = (const float*)d_in[9];
    const float* decWih  = (const float*)d_in[11];
    const float* decWhh  = (const float*)d_in[12];
    const float* decBih  = (const float*)d_in[13];
    const float* decBhh  = (const float*)d_in[14];
    const float* fcW     = (const float*)d_in[15];
    const float* fcB     = (const float*)d_in[16];
    const float* fcfW    = (const float*)d_in[17];
    const float* fcfB    = (const float*)d_in[18];
    float* out = (float*)d_out;

    cudaFuncSetAttribute(gemm_g1, cudaFuncAttributeMaxDynamicSharedMemorySize,
                         G1_SMEM_BYTES);
    cudaFuncSetAttribute(enc_fused, cudaFuncAttributeMaxDynamicSharedMemorySize,
                         ENC_SMEM_FLOATS * 4);
    cudaFuncSetAttribute(dec_fused, cudaFuncAttributeMaxDynamicSharedMemorySize,
                         DEC_SMEM_FLOATS * 4);

    prep_alpha<<<964 + BB / 2, 256>>>(X, encAttW, encWih, encWhh, decWhh, decW1,
                                      encBih, encBhh, decBih, decBhh);
    gemm_g1<<<BB * TTT / 128, 256, G1_SMEM_BYTES>>>();
    enc_fused<<<BB / 8, 1024, ENC_SMEM_FLOATS * 4>>>();
    gemm_preX16<<<BB * TTT / 128, 256, PREX_SMEM_BYTES>>>(decB1);
    dec_fused<<<BB / 8, 1024, DEC_SMEM_FLOATS * 4>>>(decWih, decW2, fcW, fcB, fcfW, fcfB, out);
}